// round 5
// baseline (speedup 1.0000x reference)
#include <cuda_runtime.h>
#include <cstdint>

// LIFNeuron dopri5 via mma.sync tf32 (3xTF32) — R5.
// vs R4: pass-split accumulators (6 indep MMA chains), pair-packed B (LDS.64),
// k5 exchanged via SMEM, cheaper time-factor (2 MUFU).

#define THREADS 256
#define S2 264              // B pair-row stride (floats), ≡ 8 (mod 32)
#define KSTR 68             // k-buffer row stride (floats), ≡ 4 (mod 32)

#define HC(x) (0.125f * (float)(x))

extern __shared__ float smf[];

// float offsets into dynamic smem
#define OFF_BPH 0                    // 32 x S2
#define OFF_BPL (OFF_BPH + 32 * S2)
#define OFF_K1  (OFF_BPL + 32 * S2)  // 8 warps x 16 x KSTR each
#define OFF_K2  (OFF_K1 + 8 * 16 * KSTR)
#define OFF_SC  (OFF_K2 + 8 * 16 * KSTR)
#define OFF_K5  (OFF_SC + 8 * 16 * KSTR)
#define OFF_BG  (OFF_K5 + 8 * 16 * KSTR)
#define SMEM_FLOATS (OFF_BG + 64)

__device__ __forceinline__ uint32_t tf32r(float a) {
    uint32_t r; asm("cvt.rna.tf32.f32 %0, %1;" : "=r"(r) : "f"(a)); return r;
}

__device__ __forceinline__ void mma8(float* d, const uint32_t* a, uint32_t b0, uint32_t b1) {
    asm volatile("mma.sync.aligned.m16n8k8.row.col.f32.tf32.tf32.f32 "
        "{%0,%1,%2,%3}, {%4,%5,%6,%7}, {%8,%9}, {%0,%1,%2,%3};"
        : "+f"(d[0]), "+f"(d[1]), "+f"(d[2]), "+f"(d[3])
        : "r"(a[0]), "r"(a[1]), "r"(a[2]), "r"(a[3]), "r"(b0), "r"(b1));
}

__device__ __forceinline__ float gelu_f(float z) {
    return 0.5f * z * (1.0f + erff(z * 0.70710678118654752440f));
}
__device__ __forceinline__ float timefac_f(float g) {
    // 1/(1+sigmoid(g)) = 1 - 1/(2 + exp(-g))
    float e = __expf(-g);
    return 1.0f - __frcp_rn(2.0f + e);
}

__global__ __launch_bounds__(THREADS, 1)
void lif_hmma_kernel(const float* __restrict__ xin,
                     const float* __restrict__ W,
                     const float* __restrict__ Wg,
                     const float* __restrict__ bgp,
                     float* __restrict__ out,
                     int batch)
{
    float* Bph = smf + OFF_BPH;     // hi of [W|Wg], pair-packed (k, k+4)
    float* Bpl = smf + OFF_BPL;     // lo
    float* BG  = smf + OFF_BG;

    const int tid = threadIdx.x;
    const int warp = tid >> 5, lane = tid & 31;
    const int r0 = lane >> 2;       // fragment row within 8
    const int c0 = lane & 3;        // thread-in-group

    // ---- init B: tf32 hi/lo split, pair-packed: Bp[p][n][q], k = (p>>2)*8 + (p&3) + 4q ----
    for (int i = tid; i < 4096; i += THREADS) {
        int k = i >> 6, n = i & 63;
        int p = ((k >> 3) << 2) | (k & 3);
        int q = (k >> 2) & 1;
        float w = W[i], g = Wg[i];
        uint32_t wh = tf32r(w), gh = tf32r(g);
        Bph[p * S2 + n * 2 + q]          = __uint_as_float(wh);
        Bpl[p * S2 + n * 2 + q]          = __uint_as_float(tf32r(w - __uint_as_float(wh)));
        Bph[p * S2 + (64 + n) * 2 + q]   = __uint_as_float(gh);
        Bpl[p * S2 + (64 + n) * 2 + q]   = __uint_as_float(tf32r(g - __uint_as_float(gh)));
    }
    if (tid < 64) BG[tid] = bgp[tid];
    for (int i = tid; i < 4 * 8 * 16 * KSTR; i += THREADS) smf[OFF_K1 + i] = 0.0f;
    __syncthreads();

    float* k1w = smf + OFF_K1 + warp * 16 * KSTR;
    float* k2w = smf + OFF_K2 + warp * 16 * KSTR;
    float* scw = smf + OFF_SC + warp * 16 * KSTR;
    float* k5w = smf + OFF_K5 + warp * 16 * KSTR;

    const int rowbase = blockIdx.x * 128 + warp * 16;

    // state in A-fragment layout: [h][m] = row (r0+8h), col (c0+4m)
    float xA[2][16], k3A[2][16], k4A[2][16];
    #pragma unroll
    for (int h = 0; h < 2; h++) {
        int rr = rowbase + r0 + 8 * h;
        if (rr >= batch) rr = batch - 1;
        #pragma unroll
        for (int m = 0; m < 16; m++) {
            xA[h][m] = xin[(size_t)rr * 64 + c0 + 4 * m];
            k3A[h][m] = 0.f; k4A[h][m] = 0.f;
        }
    }

    const float B0c = HC(35.0/384.0), B2c = HC(500.0/1113.0), B3c = HC(125.0/192.0),
                B4c = HC(-2187.0/6784.0), B5c = HC(11.0/84.0);

    #pragma unroll 1
    for (int step = 0; step < 8; step++) {
        #pragma unroll 1
        for (int s = 0; s < 6; s++) {
            float c1, c2, c3, c4, c5;
            switch (s) {
                case 0:  c1 = 0.f;                 c2 = 0.f;                 c3 = 0.f;                c4 = 0.f;              c5 = 0.f; break;
                case 1:  c1 = HC(1.0/5.0);         c2 = 0.f;                 c3 = 0.f;                c4 = 0.f;              c5 = 0.f; break;
                case 2:  c1 = HC(3.0/40.0);        c2 = HC(9.0/40.0);        c3 = 0.f;                c4 = 0.f;              c5 = 0.f; break;
                case 3:  c1 = HC(44.0/45.0);       c2 = HC(-56.0/15.0);      c3 = HC(32.0/9.0);       c4 = 0.f;              c5 = 0.f; break;
                case 4:  c1 = HC(19372.0/6561.0);  c2 = HC(-25360.0/2187.0); c3 = HC(64448.0/6561.0); c4 = HC(-212.0/729.0); c5 = 0.f; break;
                default: c1 = HC(9017.0/3168.0);   c2 = HC(-355.0/33.0);     c3 = HC(46732.0/5247.0); c4 = HC(49.0/176.0);   c5 = HC(-5103.0/18656.0); break;
            }

            // ---- build xi in A layout, tf32 hi/lo split ----
            uint32_t Ahi[2][16], Alo[2][16];
            #pragma unroll
            for (int h = 0; h < 2; h++) {
                const int ro = (r0 + 8 * h) * KSTR + c0;
                #pragma unroll
                for (int m = 0; m < 16; m++) {
                    const int off = ro + 4 * m;
                    float acc = xA[h][m];
                    acc = fmaf(c1, k1w[off], acc);
                    acc = fmaf(c2, k2w[off], acc);
                    acc = fmaf(c3, k3A[h][m], acc);
                    acc = fmaf(c4, k4A[h][m], acc);
                    acc = fmaf(c5, k5w[off], acc);
                    uint32_t hb = tf32r(acc);
                    Ahi[h][m] = hb;
                    Alo[h][m] = tf32r(acc - __uint_as_float(hb));
                }
            }

            float* dst = (s == 0) ? k1w : (s == 1) ? k2w : (s == 4) ? k5w : scw;

            // ---- MMA: 8 groups, each one z-tile + its g-tile, pass-split accums ----
            #pragma unroll 1
            for (int grp = 0; grp < 8; grp++) {
                const int nz = 8 * grp + r0;        // z column (n index)
                const int ng = 64 + 8 * grp + r0;   // g column

                float dz0[4] = {0,0,0,0}, dz1[4] = {0,0,0,0}, dz2[4] = {0,0,0,0};
                float dg0[4] = {0,0,0,0}, dg1[4] = {0,0,0,0}, dg2[4] = {0,0,0,0};

                #pragma unroll
                for (int kc = 0; kc < 8; kc++) {
                    const int p = kc * 4 + c0;
                    const float2* Bh2 = (const float2*)(Bph + p * S2);
                    const float2* Bl2 = (const float2*)(Bpl + p * S2);
                    float2 bzh = Bh2[nz], bzl = Bl2[nz];
                    float2 bgh = Bh2[ng], bgl = Bl2[ng];

                    uint32_t ah[4] = {Ahi[0][2*kc], Ahi[1][2*kc], Ahi[0][2*kc+1], Ahi[1][2*kc+1]};
                    uint32_t al[4] = {Alo[0][2*kc], Alo[1][2*kc], Alo[0][2*kc+1], Alo[1][2*kc+1]};

                    mma8(dz0, ah, __float_as_uint(bzh.x), __float_as_uint(bzh.y));
                    mma8(dz1, ah, __float_as_uint(bzl.x), __float_as_uint(bzl.y));
                    mma8(dz2, al, __float_as_uint(bzh.x), __float_as_uint(bzh.y));
                    mma8(dg0, ah, __float_as_uint(bgh.x), __float_as_uint(bgh.y));
                    mma8(dg1, ah, __float_as_uint(bgl.x), __float_as_uint(bgl.y));
                    mma8(dg2, al, __float_as_uint(bgh.x), __float_as_uint(bgh.y));
                }

                const float bga = BG[8 * grp + 2 * c0];
                const float bgb = BG[8 * grp + 2 * c0 + 1];
                float kv[4];
                #pragma unroll
                for (int e = 0; e < 4; e++) {
                    float z = (dz0[e] + dz1[e]) + dz2[e];
                    float g = (dg0[e] + dg1[e]) + dg2[e];
                    g += (e & 1) ? bgb : bga;
                    kv[e] = gelu_f(z) * timefac_f(g);
                }
                *(float2*)&dst[r0 * KSTR + 8 * grp + 2 * c0]       = make_float2(kv[0], kv[1]);
                *(float2*)&dst[(r0 + 8) * KSTR + 8 * grp + 2 * c0] = make_float2(kv[2], kv[3]);
            }

            __syncwarp();

            // ---- stage epilogue ----
            if (s == 2) {
                #pragma unroll
                for (int h = 0; h < 2; h++) {
                    const int ro = (r0 + 8 * h) * KSTR + c0;
                    #pragma unroll
                    for (int m = 0; m < 16; m++) k3A[h][m] = scw[ro + 4 * m];
                }
            } else if (s == 3) {
                #pragma unroll
                for (int h = 0; h < 2; h++) {
                    const int ro = (r0 + 8 * h) * KSTR + c0;
                    #pragma unroll
                    for (int m = 0; m < 16; m++) k4A[h][m] = scw[ro + 4 * m];
                }
            } else if (s == 5) {
                #pragma unroll
                for (int h = 0; h < 2; h++) {
                    const int ro = (r0 + 8 * h) * KSTR + c0;
                    #pragma unroll
                    for (int m = 0; m < 16; m++) {
                        const int off = ro + 4 * m;
                        float a = xA[h][m];
                        a = fmaf(B0c, k1w[off], a);
                        a = fmaf(B2c, k3A[h][m], a);
                        a = fmaf(B3c, k4A[h][m], a);
                        a = fmaf(B4c, k5w[off], a);
                        xA[h][m] = fmaf(B5c, scw[off], a);   // scw holds k6
                    }
                }
            }
            __syncwarp();
        }
    }

    // ---- spike output ----
    #pragma unroll
    for (int h = 0; h < 2; h++) {
        int rr = rowbase + r0 + 8 * h;
        if (rr < batch) {
            #pragma unroll
            for (int m = 0; m < 16; m++)
                out[(size_t)rr * 64 + c0 + 4 * m] = ((xA[h][m] - 0.3f) > 0.0f) ? 1.0f : 0.0f;
        }
    }
}

extern "C" void kernel_launch(void* const* d_in, const int* in_sizes, int n_in,
                              void* d_out, int out_size)
{
    const float* x  = (const float*)d_in[0];   // [batch, 64]
    const float* W  = (const float*)d_in[1];   // [64, 64]
    const float* Wg = (const float*)d_in[2];   // [64, 64]
    const float* bg = (const float*)d_in[3];   // [64]
    float* out = (float*)d_out;

    const int smem_bytes = SMEM_FLOATS * 4;
    cudaFuncSetAttribute(lif_hmma_kernel, cudaFuncAttributeMaxDynamicSharedMemorySize, smem_bytes);

    int batch = in_sizes[0] / 64;
    int grid = (batch + 127) / 128;
    lif_hmma_kernel<<<grid, THREADS, smem_bytes>>>(x, W, Wg, bg, out, batch);
}

// round 6
// speedup vs baseline: 1.5690x; 1.5690x over previous
#include <cuda_runtime.h>
#include <cstdint>

// LIFNeuron dopri5 via mma.sync tf32 (3xTF32) — R6.
// = R4 structure with: grp loop fully unrolled (cross-group MMA/epilogue overlap),
//   k5 exchanged via SMEM (-32 regs), __expf 1-rcp time factor (R5-validated).

#define THREADS 256
#define BSTR 136            // B smem row stride (floats): ≡8 (mod 32), conflict-free
#define KSTR 68             // k-buffer row stride: ≡4 (mod 32), conflict-free

#define HC(x) (0.125f * (float)(x))

extern __shared__ float smf[];

#define OFF_BH 0
#define OFF_BL (OFF_BH + 64 * BSTR)
#define OFF_K1 (OFF_BL + 64 * BSTR)
#define OFF_K2 (OFF_K1 + 8 * 16 * KSTR)
#define OFF_SC (OFF_K2 + 8 * 16 * KSTR)
#define OFF_K5 (OFF_SC + 8 * 16 * KSTR)
#define OFF_BG (OFF_K5 + 8 * 16 * KSTR)
#define SMEM_FLOATS (OFF_BG + 64)

__device__ __forceinline__ uint32_t tf32r(float a) {
    uint32_t r; asm("cvt.rna.tf32.f32 %0, %1;" : "=r"(r) : "f"(a)); return r;
}

__device__ __forceinline__ void mma8(float* d, const uint32_t* a, uint32_t b0, uint32_t b1) {
    asm volatile("mma.sync.aligned.m16n8k8.row.col.f32.tf32.tf32.f32 "
        "{%0,%1,%2,%3}, {%4,%5,%6,%7}, {%8,%9}, {%0,%1,%2,%3};"
        : "+f"(d[0]), "+f"(d[1]), "+f"(d[2]), "+f"(d[3])
        : "r"(a[0]), "r"(a[1]), "r"(a[2]), "r"(a[3]), "r"(b0), "r"(b1));
}

__device__ __forceinline__ float gelu_f(float z) {
    return 0.5f * z * (1.0f + erff(z * 0.70710678118654752440f));
}
__device__ __forceinline__ float timefac_f(float g) {
    // 1/(1+sigmoid(g)) = 1 - 1/(2 + exp(-g))   (validated: rel_err 0.0 in R5)
    float e = __expf(-g);
    return 1.0f - __frcp_rn(2.0f + e);
}

__global__ __launch_bounds__(THREADS, 1)
void lif_hmma_kernel(const float* __restrict__ xin,
                     const float* __restrict__ W,
                     const float* __restrict__ Wg,
                     const float* __restrict__ bgp,
                     float* __restrict__ out,
                     int batch)
{
    float* Bh = smf + OFF_BH;       // [64][BSTR], cols 0-63 = W, 64-127 = Wg (tf32 hi)
    float* Bl = smf + OFF_BL;       // tf32 lo
    float* BG = smf + OFF_BG;

    const int tid = threadIdx.x;
    const int warp = tid >> 5, lane = tid & 31;
    const int r0 = lane >> 2;
    const int c0 = lane & 3;

    for (int i = tid; i < 4096; i += THREADS) {
        int k = i >> 6, n = i & 63;
        float w = W[i], g = Wg[i];
        uint32_t wh = tf32r(w), gh = tf32r(g);
        Bh[k * BSTR + n]      = __uint_as_float(wh);
        Bl[k * BSTR + n]      = __uint_as_float(tf32r(w - __uint_as_float(wh)));
        Bh[k * BSTR + 64 + n] = __uint_as_float(gh);
        Bl[k * BSTR + 64 + n] = __uint_as_float(tf32r(g - __uint_as_float(gh)));
    }
    if (tid < 64) BG[tid] = bgp[tid];
    for (int i = tid; i < 4 * 8 * 16 * KSTR; i += THREADS) smf[OFF_K1 + i] = 0.0f;
    __syncthreads();

    float* k1w = smf + OFF_K1 + warp * 16 * KSTR;
    float* k2w = smf + OFF_K2 + warp * 16 * KSTR;
    float* scw = smf + OFF_SC + warp * 16 * KSTR;
    float* k5w = smf + OFF_K5 + warp * 16 * KSTR;

    const int rowbase = blockIdx.x * 128 + warp * 16;

    // state in A-fragment layout: [h][m] = row (r0+8h), col (c0+4m)
    float xA[2][16], k3A[2][16], k4A[2][16];
    #pragma unroll
    for (int h = 0; h < 2; h++) {
        int rr = rowbase + r0 + 8 * h;
        if (rr >= batch) rr = batch - 1;
        #pragma unroll
        for (int m = 0; m < 16; m++) {
            xA[h][m] = xin[(size_t)rr * 64 + c0 + 4 * m];
            k3A[h][m] = 0.f; k4A[h][m] = 0.f;
        }
    }

    const float B0c = HC(35.0/384.0), B2c = HC(500.0/1113.0), B3c = HC(125.0/192.0),
                B4c = HC(-2187.0/6784.0), B5c = HC(11.0/84.0);

    #pragma unroll 1
    for (int step = 0; step < 8; step++) {
        #pragma unroll 1
        for (int s = 0; s < 6; s++) {
            float c1, c2, c3, c4, c5;
            switch (s) {
                case 0:  c1 = 0.f;                 c2 = 0.f;                 c3 = 0.f;                c4 = 0.f;              c5 = 0.f; break;
                case 1:  c1 = HC(1.0/5.0);         c2 = 0.f;                 c3 = 0.f;                c4 = 0.f;              c5 = 0.f; break;
                case 2:  c1 = HC(3.0/40.0);        c2 = HC(9.0/40.0);        c3 = 0.f;                c4 = 0.f;              c5 = 0.f; break;
                case 3:  c1 = HC(44.0/45.0);       c2 = HC(-56.0/15.0);      c3 = HC(32.0/9.0);       c4 = 0.f;              c5 = 0.f; break;
                case 4:  c1 = HC(19372.0/6561.0);  c2 = HC(-25360.0/2187.0); c3 = HC(64448.0/6561.0); c4 = HC(-212.0/729.0); c5 = 0.f; break;
                default: c1 = HC(9017.0/3168.0);   c2 = HC(-355.0/33.0);     c3 = HC(46732.0/5247.0); c4 = HC(49.0/176.0);   c5 = HC(-5103.0/18656.0); break;
            }

            // ---- build xi in A layout, tf32 hi/lo split ----
            uint32_t Ahi[2][16], Alo[2][16];
            #pragma unroll
            for (int h = 0; h < 2; h++) {
                const int ro = (r0 + 8 * h) * KSTR + c0;
                #pragma unroll
                for (int m = 0; m < 16; m++) {
                    const int off = ro + 4 * m;
                    float acc = xA[h][m];
                    acc = fmaf(c1, k1w[off], acc);
                    acc = fmaf(c2, k2w[off], acc);
                    acc = fmaf(c3, k3A[h][m], acc);
                    acc = fmaf(c4, k4A[h][m], acc);
                    acc = fmaf(c5, k5w[off], acc);
                    uint32_t hb = tf32r(acc);
                    Ahi[h][m] = hb;
                    Alo[h][m] = tf32r(acc - __uint_as_float(hb));
                }
            }

            float* dst = (s == 0) ? k1w : (s == 1) ? k2w : (s == 4) ? k5w : scw;

            // ---- MMA: 4 groups x 4 n-tiles, FULLY UNROLLED for cross-grp overlap ----
            #pragma unroll
            for (int grp = 0; grp < 4; grp++) {
                const int nb0 = 16 * grp;         // z tile j
                const int nb1 = 64 + nb0;         // paired g tile
                const int nb2 = nb0 + 8;          // z tile j+1
                const int nb3 = 64 + nb2;

                float d0[4] = {0,0,0,0}, d1[4] = {0,0,0,0};
                float d2[4] = {0,0,0,0}, d3[4] = {0,0,0,0};

                #pragma unroll
                for (int kc = 0; kc < 8; kc++) {
                    const int bb = (kc * 8 + c0) * BSTR + r0;
                    uint32_t bh0_0 = __float_as_uint(Bh[bb + nb0]);
                    uint32_t bh1_0 = __float_as_uint(Bh[bb + 4 * BSTR + nb0]);
                    uint32_t bl0_0 = __float_as_uint(Bl[bb + nb0]);
                    uint32_t bl1_0 = __float_as_uint(Bl[bb + 4 * BSTR + nb0]);
                    uint32_t bh0_1 = __float_as_uint(Bh[bb + nb1]);
                    uint32_t bh1_1 = __float_as_uint(Bh[bb + 4 * BSTR + nb1]);
                    uint32_t bl0_1 = __float_as_uint(Bl[bb + nb1]);
                    uint32_t bl1_1 = __float_as_uint(Bl[bb + 4 * BSTR + nb1]);
                    uint32_t bh0_2 = __float_as_uint(Bh[bb + nb2]);
                    uint32_t bh1_2 = __float_as_uint(Bh[bb + 4 * BSTR + nb2]);
                    uint32_t bl0_2 = __float_as_uint(Bl[bb + nb2]);
                    uint32_t bl1_2 = __float_as_uint(Bl[bb + 4 * BSTR + nb2]);
                    uint32_t bh0_3 = __float_as_uint(Bh[bb + nb3]);
                    uint32_t bh1_3 = __float_as_uint(Bh[bb + 4 * BSTR + nb3]);
                    uint32_t bl0_3 = __float_as_uint(Bl[bb + nb3]);
                    uint32_t bl1_3 = __float_as_uint(Bl[bb + 4 * BSTR + nb3]);

                    uint32_t ah[4] = {Ahi[0][2*kc], Ahi[1][2*kc], Ahi[0][2*kc+1], Ahi[1][2*kc+1]};
                    uint32_t al[4] = {Alo[0][2*kc], Alo[1][2*kc], Alo[0][2*kc+1], Alo[1][2*kc+1]};

                    mma8(d0, ah, bh0_0, bh1_0);
                    mma8(d1, ah, bh0_1, bh1_1);
                    mma8(d2, ah, bh0_2, bh1_2);
                    mma8(d3, ah, bh0_3, bh1_3);
                    mma8(d0, ah, bl0_0, bl1_0);
                    mma8(d1, ah, bl0_1, bl1_1);
                    mma8(d2, ah, bl0_2, bl1_2);
                    mma8(d3, ah, bl0_3, bl1_3);
                    mma8(d0, al, bh0_0, bh1_0);
                    mma8(d1, al, bh0_1, bh1_1);
                    mma8(d2, al, bh0_2, bh1_2);
                    mma8(d3, al, bh0_3, bh1_3);
                }

                {
                    float bga = BG[nb0 + 2 * c0], bgb = BG[nb0 + 2 * c0 + 1];
                    float kv0 = gelu_f(d0[0]) * timefac_f(d1[0] + bga);
                    float kv1 = gelu_f(d0[1]) * timefac_f(d1[1] + bgb);
                    float kv2 = gelu_f(d0[2]) * timefac_f(d1[2] + bga);
                    float kv3 = gelu_f(d0[3]) * timefac_f(d1[3] + bgb);
                    *(float2*)&dst[r0 * KSTR + nb0 + 2 * c0]       = make_float2(kv0, kv1);
                    *(float2*)&dst[(r0 + 8) * KSTR + nb0 + 2 * c0] = make_float2(kv2, kv3);
                }
                {
                    float bga = BG[nb2 + 2 * c0], bgb = BG[nb2 + 2 * c0 + 1];
                    float kv0 = gelu_f(d2[0]) * timefac_f(d3[0] + bga);
                    float kv1 = gelu_f(d2[1]) * timefac_f(d3[1] + bgb);
                    float kv2 = gelu_f(d2[2]) * timefac_f(d3[2] + bga);
                    float kv3 = gelu_f(d2[3]) * timefac_f(d3[3] + bgb);
                    *(float2*)&dst[r0 * KSTR + nb2 + 2 * c0]       = make_float2(kv0, kv1);
                    *(float2*)&dst[(r0 + 8) * KSTR + nb2 + 2 * c0] = make_float2(kv2, kv3);
                }
            }

            __syncwarp();

            // ---- stage epilogue ----
            if (s == 2) {
                #pragma unroll
                for (int h = 0; h < 2; h++) {
                    const int ro = (r0 + 8 * h) * KSTR + c0;
                    #pragma unroll
                    for (int m = 0; m < 16; m++) k3A[h][m] = scw[ro + 4 * m];
                }
            } else if (s == 3) {
                #pragma unroll
                for (int h = 0; h < 2; h++) {
                    const int ro = (r0 + 8 * h) * KSTR + c0;
                    #pragma unroll
                    for (int m = 0; m < 16; m++) k4A[h][m] = scw[ro + 4 * m];
                }
            } else if (s == 5) {
                #pragma unroll
                for (int h = 0; h < 2; h++) {
                    const int ro = (r0 + 8 * h) * KSTR + c0;
                    #pragma unroll
                    for (int m = 0; m < 16; m++) {
                        const int off = ro + 4 * m;
                        float a = xA[h][m];
                        a = fmaf(B0c, k1w[off], a);
                        a = fmaf(B2c, k3A[h][m], a);
                        a = fmaf(B3c, k4A[h][m], a);
                        a = fmaf(B4c, k5w[off], a);
                        xA[h][m] = fmaf(B5c, scw[off], a);   // scw holds k6
                    }
                }
            }
            __syncwarp();
        }
    }

    // ---- spike output ----
    #pragma unroll
    for (int h = 0; h < 2; h++) {
        int rr = rowbase + r0 + 8 * h;
        if (rr < batch) {
            #pragma unroll
            for (int m = 0; m < 16; m++)
                out[(size_t)rr * 64 + c0 + 4 * m] = ((xA[h][m] - 0.3f) > 0.0f) ? 1.0f : 0.0f;
        }
    }
}

extern "C" void kernel_launch(void* const* d_in, const int* in_sizes, int n_in,
                              void* d_out, int out_size)
{
    const float* x  = (const float*)d_in[0];   // [batch, 64]
    const float* W  = (const float*)d_in[1];   // [64, 64]
    const float* Wg = (const float*)d_in[2];   // [64, 64]
    const float* bg = (const float*)d_in[3];   // [64]
    float* out = (float*)d_out;

    const int smem_bytes = SMEM_FLOATS * 4;
    cudaFuncSetAttribute(lif_hmma_kernel, cudaFuncAttributeMaxDynamicSharedMemorySize, smem_bytes);

    int batch = in_sizes[0] / 64;
    int grid = (batch + 127) / 128;
    lif_hmma_kernel<<<grid, THREADS, smem_bytes>>>(x, W, Wg, bg, out, batch);
}

// round 9
// speedup vs baseline: 1.5942x; 1.0160x over previous
#include <cuda_runtime.h>
#include <cstdint>

// LIFNeuron dopri5 via mma.sync tf32 (3xTF32) — R7.
// = R6 with quad-packed B: one LDS.128 per (n-tile, kc) yields
// {Bhi[k], Bhi[k+4], Blo[k], Blo[k+4]} -> B-load issues 512 -> 128 per stage.

#define THREADS 256
#define BQS 130             // B quad-row stride in float4 (520 floats ≡ 8 mod 32)
#define KSTR 68             // k-buffer row stride: ≡4 (mod 32)

#define HC(x) (0.125f * (float)(x))

extern __shared__ float smf[];

#define OFF_BQ 0                         // 32 rows x BQS float4
#define OFF_K1 (32 * BQS * 4)
#define OFF_K2 (OFF_K1 + 8 * 16 * KSTR)
#define OFF_SC (OFF_K2 + 8 * 16 * KSTR)
#define OFF_K5 (OFF_SC + 8 * 16 * KSTR)
#define OFF_BG (OFF_K5 + 8 * 16 * KSTR)
#define SMEM_FLOATS (OFF_BG + 64)

__device__ __forceinline__ uint32_t tf32r(float a) {
    uint32_t r; asm("cvt.rna.tf32.f32 %0, %1;" : "=r"(r) : "f"(a)); return r;
}

__device__ __forceinline__ void mma8(float* d, const uint32_t* a, uint32_t b0, uint32_t b1) {
    asm volatile("mma.sync.aligned.m16n8k8.row.col.f32.tf32.tf32.f32 "
        "{%0,%1,%2,%3}, {%4,%5,%6,%7}, {%8,%9}, {%0,%1,%2,%3};"
        : "+f"(d[0]), "+f"(d[1]), "+f"(d[2]), "+f"(d[3])
        : "r"(a[0]), "r"(a[1]), "r"(a[2]), "r"(a[3]), "r"(b0), "r"(b1));
}

__device__ __forceinline__ float gelu_f(float z) {
    return 0.5f * z * (1.0f + erff(z * 0.70710678118654752440f));
}
__device__ __forceinline__ float timefac_f(float g) {
    float e = __expf(-g);
    return 1.0f - __frcp_rn(2.0f + e);
}

__global__ __launch_bounds__(THREADS, 1)
void lif_hmma_kernel(const float* __restrict__ xin,
                     const float* __restrict__ W,
                     const float* __restrict__ Wg,
                     const float* __restrict__ bgp,
                     float* __restrict__ out,
                     int batch)
{
    float4* Bq = (float4*)(smf + OFF_BQ);   // [p=kc*4+c0][n], n 0-63 = W, 64-127 = Wg
    float*  BG = smf + OFF_BG;

    const int tid = threadIdx.x;
    const int warp = tid >> 5, lane = tid & 31;
    const int r0 = lane >> 2;
    const int c0 = lane & 3;

    // ---- init Bq: {hi(k), hi(k+4), lo(k), lo(k+4)} at p = (k>>3)*4 + (k&3) ----
    for (int i = tid; i < 4096; i += THREADS) {
        int k = i >> 6, n = i & 63;
        int p = ((k >> 3) << 2) | (k & 3);
        int slot = (k & 4) ? 1 : 0;          // 0: .x/.z, 1: .y/.w
        float w = W[i], g = Wg[i];
        uint32_t wh = tf32r(w), gh = tf32r(g);
        float* cw = (float*)&Bq[p * BQS + n];
        float* cg = (float*)&Bq[p * BQS + 64 + n];
        cw[slot]     = __uint_as_float(wh);
        cw[slot + 2] = __uint_as_float(tf32r(w - __uint_as_float(wh)));
        cg[slot]     = __uint_as_float(gh);
        cg[slot + 2] = __uint_as_float(tf32r(g - __uint_as_float(gh)));
    }
    if (tid < 64) BG[tid] = bgp[tid];
    for (int i = tid; i < 4 * 8 * 16 * KSTR; i += THREADS) smf[OFF_K1 + i] = 0.0f;
    __syncthreads();

    float* k1w = smf + OFF_K1 + warp * 16 * KSTR;
    float* k2w = smf + OFF_K2 + warp * 16 * KSTR;
    float* scw = smf + OFF_SC + warp * 16 * KSTR;
    float* k5w = smf + OFF_K5 + warp * 16 * KSTR;

    const int rowbase = blockIdx.x * 128 + warp * 16;

    // state in A-fragment layout: [h][m] = row (r0+8h), col (c0+4m)
    float xA[2][16], k3A[2][16], k4A[2][16];
    #pragma unroll
    for (int h = 0; h < 2; h++) {
        int rr = rowbase + r0 + 8 * h;
        if (rr >= batch) rr = batch - 1;
        #pragma unroll
        for (int m = 0; m < 16; m++) {
            xA[h][m] = xin[(size_t)rr * 64 + c0 + 4 * m];
            k3A[h][m] = 0.f; k4A[h][m] = 0.f;
        }
    }

    const float B0c = HC(35.0/384.0), B2c = HC(500.0/1113.0), B3c = HC(125.0/192.0),
                B4c = HC(-2187.0/6784.0), B5c = HC(11.0/84.0);

    // per-thread base into Bq for this c0
    const float4* BqT = Bq + c0 * BQS;

    #pragma unroll 1
    for (int step = 0; step < 8; step++) {
        #pragma unroll 1
        for (int s = 0; s < 6; s++) {
            float c1, c2, c3, c4, c5;
            switch (s) {
                case 0:  c1 = 0.f;                 c2 = 0.f;                 c3 = 0.f;                c4 = 0.f;              c5 = 0.f; break;
                case 1:  c1 = HC(1.0/5.0);         c2 = 0.f;                 c3 = 0.f;                c4 = 0.f;              c5 = 0.f; break;
                case 2:  c1 = HC(3.0/40.0);        c2 = HC(9.0/40.0);        c3 = 0.f;                c4 = 0.f;              c5 = 0.f; break;
                case 3:  c1 = HC(44.0/45.0);       c2 = HC(-56.0/15.0);      c3 = HC(32.0/9.0);       c4 = 0.f;              c5 = 0.f; break;
                case 4:  c1 = HC(19372.0/6561.0);  c2 = HC(-25360.0/2187.0); c3 = HC(64448.0/6561.0); c4 = HC(-212.0/729.0); c5 = 0.f; break;
                default: c1 = HC(9017.0/3168.0);   c2 = HC(-355.0/33.0);     c3 = HC(46732.0/5247.0); c4 = HC(49.0/176.0);   c5 = HC(-5103.0/18656.0); break;
            }

            // ---- build xi in A layout, tf32 hi/lo split ----
            uint32_t Ahi[2][16], Alo[2][16];
            #pragma unroll
            for (int h = 0; h < 2; h++) {
                const int ro = (r0 + 8 * h) * KSTR + c0;
                #pragma unroll
                for (int m = 0; m < 16; m++) {
                    const int off = ro + 4 * m;
                    float acc = xA[h][m];
                    acc = fmaf(c1, k1w[off], acc);
                    acc = fmaf(c2, k2w[off], acc);
                    acc = fmaf(c3, k3A[h][m], acc);
                    acc = fmaf(c4, k4A[h][m], acc);
                    acc = fmaf(c5, k5w[off], acc);
                    uint32_t hb = tf32r(acc);
                    Ahi[h][m] = hb;
                    Alo[h][m] = tf32r(acc - __uint_as_float(hb));
                }
            }

            float* dst = (s == 0) ? k1w : (s == 1) ? k2w : (s == 4) ? k5w : scw;

            // ---- MMA: 4 groups x 4 n-tiles, fully unrolled; 1 LDS.128 per tile/kc ----
            #pragma unroll
            for (int grp = 0; grp < 4; grp++) {
                const int nb0 = 16 * grp + r0;     // z tile j  (col n)
                const int nb2 = nb0 + 8;           // z tile j+1
                const int nb1 = 64 + nb0;          // g tile j
                const int nb3 = 64 + nb2;          // g tile j+1

                float d0[4] = {0,0,0,0}, d1[4] = {0,0,0,0};
                float d2[4] = {0,0,0,0}, d3[4] = {0,0,0,0};

                #pragma unroll
                for (int kc = 0; kc < 8; kc++) {
                    const float4* Bp = BqT + (size_t)(kc * 4) * BQS;
                    float4 q0 = Bp[nb0];   // {hi k, hi k+4, lo k, lo k+4}
                    float4 q1 = Bp[nb1];
                    float4 q2 = Bp[nb2];
                    float4 q3 = Bp[nb3];

                    uint32_t ah[4] = {Ahi[0][2*kc], Ahi[1][2*kc], Ahi[0][2*kc+1], Ahi[1][2*kc+1]};
                    uint32_t al[4] = {Alo[0][2*kc], Alo[1][2*kc], Alo[0][2*kc+1], Alo[1][2*kc+1]};

                    mma8(d0, ah, __float_as_uint(q0.x), __float_as_uint(q0.y));  // HH
                    mma8(d1, ah, __float_as_uint(q1.x), __float_as_uint(q1.y));
                    mma8(d2, ah, __float_as_uint(q2.x), __float_as_uint(q2.y));
                    mma8(d3, ah, __float_as_uint(q3.x), __float_as_uint(q3.y));
                    mma8(d0, ah, __float_as_uint(q0.z), __float_as_uint(q0.w));  // HL
                    mma8(d1, ah, __float_as_uint(q1.z), __float_as_uint(q1.w));
                    mma8(d2, ah, __float_as_uint(q2.z), __float_as_uint(q2.w));
                    mma8(d3, ah, __float_as_uint(q3.z), __float_as_uint(q3.w));
                    mma8(d0, al, __float_as_uint(q0.x), __float_as_uint(q0.y));  // LH
                    mma8(d1, al, __float_as_uint(q1.x), __float_as_uint(q1.y));
                    mma8(d2, al, __float_as_uint(q2.x), __float_as_uint(q2.y));
                    mma8(d3, al, __float_as_uint(q3.x), __float_as_uint(q3.y));
                }

                const int nb = 16 * grp;
                {
                    float bga = BG[nb + 2 * c0], bgb = BG[nb + 2 * c0 + 1];
                    float kv0 = gelu_f(d0[0]) * timefac_f(d1[0] + bga);
                    float kv1 = gelu_f(d0[1]) * timefac_f(d1[1] + bgb);
                    float kv2 = gelu_f(d0[2]) * timefac_f(d1[2] + bga);
                    float kv3 = gelu_f(d0[3]) * timefac_f(d1[3] + bgb);
                    *(float2*)&dst[r0 * KSTR + nb + 2 * c0]       = make_float2(kv0, kv1);
                    *(float2*)&dst[(r0 + 8) * KSTR + nb + 2 * c0] = make_float2(kv2, kv3);
                }
                {
                    float bga = BG[nb + 8 + 2 * c0], bgb = BG[nb + 8 + 2 * c0 + 1];
                    float kv0 = gelu_f(d2[0]) * timefac_f(d3[0] + bga);
                    float kv1 = gelu_f(d2[1]) * timefac_f(d3[1] + bgb);
                    float kv2 = gelu_f(d2[2]) * timefac_f(d3[2] + bga);
                    float kv3 = gelu_f(d2[3]) * timefac_f(d3[3] + bgb);
                    *(float2*)&dst[r0 * KSTR + nb + 8 + 2 * c0]       = make_float2(kv0, kv1);
                    *(float2*)&dst[(r0 + 8) * KSTR + nb + 8 + 2 * c0] = make_float2(kv2, kv3);
                }
            }

            __syncwarp();

            // ---- stage epilogue ----
            if (s == 2) {
                #pragma unroll
                for (int h = 0; h < 2; h++) {
                    const int ro = (r0 + 8 * h) * KSTR + c0;
                    #pragma unroll
                    for (int m = 0; m < 16; m++) k3A[h][m] = scw[ro + 4 * m];
                }
            } else if (s == 3) {
                #pragma unroll
                for (int h = 0; h < 2; h++) {
                    const int ro = (r0 + 8 * h) * KSTR + c0;
                    #pragma unroll
                    for (int m = 0; m < 16; m++) k4A[h][m] = scw[ro + 4 * m];
                }
            } else if (s == 5) {
                #pragma unroll
                for (int h = 0; h < 2; h++) {
                    const int ro = (r0 + 8 * h) * KSTR + c0;
                    #pragma unroll
                    for (int m = 0; m < 16; m++) {
                        const int off = ro + 4 * m;
                        float a = xA[h][m];
                        a = fmaf(B0c, k1w[off], a);
                        a = fmaf(B2c, k3A[h][m], a);
                        a = fmaf(B3c, k4A[h][m], a);
                        a = fmaf(B4c, k5w[off], a);
                        xA[h][m] = fmaf(B5c, scw[off], a);   // scw holds k6
                    }
                }
            }
            __syncwarp();
        }
    }

    // ---- spike output ----
    #pragma unroll
    for (int h = 0; h < 2; h++) {
        int rr = rowbase + r0 + 8 * h;
        if (rr < batch) {
            #pragma unroll
            for (int m = 0; m < 16; m++)
                out[(size_t)rr * 64 + c0 + 4 * m] = ((xA[h][m] - 0.3f) > 0.0f) ? 1.0f : 0.0f;
        }
    }
}

extern "C" void kernel_launch(void* const* d_in, const int* in_sizes, int n_in,
                              void* d_out, int out_size)
{
    const float* x  = (const float*)d_in[0];   // [batch, 64]
    const float* W  = (const float*)d_in[1];   // [64, 64]
    const float* Wg = (const float*)d_in[2];   // [64, 64]
    const float* bg = (const float*)d_in[3];   // [64]
    float* out = (float*)d_out;

    const int smem_bytes = SMEM_FLOATS * 4;
    cudaFuncSetAttribute(lif_hmma_kernel, cudaFuncAttributeMaxDynamicSharedMemorySize, smem_bytes);

    int batch = in_sizes[0] / 64;
    int grid = (batch + 127) / 128;
    lif_hmma_kernel<<<grid, THREADS, smem_bytes>>>(x, W, Wg, bg, out, batch);
}

// round 11
// speedup vs baseline: 2.1577x; 1.3535x over previous
#include <cuda_runtime.h>
#include <cuda_fp16.h>
#include <cstdint>

// LIFNeuron dopri5 via mma.sync m16n8k16 fp16 (2-term split, 3 passes) — R10.
// Same error class as 3xTF32 (both splits carry 22 mantissa bits) at half the
// MMA instruction count and half the per-chain depth.

#define THREADS 256
#define BQS 130             // B row stride in float4 (≡2 mod 8 -> conflict-free LDS.128)
#define KSTR 72             // k-buffer row stride in floats (≡8 mod 32 -> conflict-free LDS.64)

#define HC(x) (0.125f * (float)(x))

extern __shared__ float smf[];

#define OFF_BQ 0                          // 16 rows x BQS float4 = 8320 floats
#define OFF_K1 (16 * BQS * 4)
#define KBUF   (8 * 16 * KSTR)            // 9216 floats per buffer (8 warps)
#define OFF_K2 (OFF_K1 + KBUF)
#define OFF_SC (OFF_K2 + KBUF)
#define OFF_K5 (OFF_SC + KBUF)
#define OFF_BG (OFF_K5 + KBUF)
#define SMEM_FLOATS (OFF_BG + 64)

__device__ __forceinline__ void mma16(float* d, const uint32_t* a, uint32_t b0, uint32_t b1) {
    asm volatile("mma.sync.aligned.m16n8k16.row.col.f32.f16.f16.f32 "
        "{%0,%1,%2,%3}, {%4,%5,%6,%7}, {%8,%9}, {%0,%1,%2,%3};"
        : "+f"(d[0]), "+f"(d[1]), "+f"(d[2]), "+f"(d[3])
        : "r"(a[0]), "r"(a[1]), "r"(a[2]), "r"(a[3]), "r"(b0), "r"(b1));
}

__device__ __forceinline__ float gelu_f(float z) {
    return 0.5f * z * (1.0f + erff(z * 0.70710678118654752440f));
}
__device__ __forceinline__ float timefac_f(float g) {
    float e = __expf(-g);
    return 1.0f - __frcp_rn(2.0f + e);
}

__global__ __launch_bounds__(THREADS, 1)
void lif_hmma_kernel(const float* __restrict__ xin,
                     const float* __restrict__ W,
                     const float* __restrict__ Wg,
                     const float* __restrict__ bgp,
                     float* __restrict__ out,
                     int batch)
{
    float4* Bq = (float4*)(smf + OFF_BQ);   // [p = kc*4+c0][n]: 8 halves {h1 k0,k0+1,k0+8,k0+9, h2 ...}
    float*  BG = smf + OFF_BG;

    const int tid = threadIdx.x;
    const int warp = tid >> 5, lane = tid & 31;
    const int r0 = lane >> 2;
    const int c0 = lane & 3;

    // ---- init B: fp16 hi/lo split of [W|Wg], fragment-packed for m16n8k16 ----
    for (int i = tid; i < 4096; i += THREADS) {
        int k = i >> 6, n = i & 63;
        int p = ((k >> 4) << 2) | ((k >> 1) & 3);
        int slot = ((k >> 3) & 1) * 2 + (k & 1);
        float w = W[i], g = Wg[i];
        __half wh = __float2half_rn(w);
        __half wl = __float2half_rn(w - __half2float(wh));
        __half gh = __float2half_rn(g);
        __half gl = __float2half_rn(g - __half2float(gh));
        __half* cw = (__half*)(Bq + p * BQS + n);
        __half* cg = (__half*)(Bq + p * BQS + 64 + n);
        cw[slot] = wh; cw[slot + 4] = wl;
        cg[slot] = gh; cg[slot + 4] = gl;
    }
    if (tid < 64) BG[tid] = bgp[tid];
    for (int i = tid; i < 4 * KBUF; i += THREADS) smf[OFF_K1 + i] = 0.0f;
    __syncthreads();

    float* k1w = smf + OFF_K1 + warp * 16 * KSTR;
    float* k2w = smf + OFF_K2 + warp * 16 * KSTR;
    float* scw = smf + OFF_SC + warp * 16 * KSTR;
    float* k5w = smf + OFF_K5 + warp * 16 * KSTR;

    const int rowbase = blockIdx.x * 128 + warp * 16;

    // A-side state: xA[h][m], m = kc*4 + e*2 + d  ->  col = 16*kc + 8*e + 2*c0 + d
    float xA[2][16], k3A[2][16], k4A[2][16];
    #pragma unroll
    for (int h = 0; h < 2; h++) {
        int rr = rowbase + r0 + 8 * h;
        if (rr >= batch) rr = batch - 1;
        #pragma unroll
        for (int kc = 0; kc < 4; kc++)
            #pragma unroll
            for (int e = 0; e < 2; e++) {
                int m = kc * 4 + e * 2;
                int col = 16 * kc + 8 * e + 2 * c0;
                float2 v = *(const float2*)(xin + (size_t)rr * 64 + col);
                xA[h][m] = v.x; xA[h][m + 1] = v.y;
                k3A[h][m] = 0.f; k3A[h][m + 1] = 0.f;
                k4A[h][m] = 0.f; k4A[h][m + 1] = 0.f;
            }
    }

    const float B0c = HC(35.0/384.0), B2c = HC(500.0/1113.0), B3c = HC(125.0/192.0),
                B4c = HC(-2187.0/6784.0), B5c = HC(11.0/84.0);

    const float4* BqT = Bq + c0 * BQS;

    #pragma unroll 1
    for (int step = 0; step < 8; step++) {
        #pragma unroll 1
        for (int s = 0; s < 6; s++) {
            float c1, c2, c3, c4, c5;
            switch (s) {
                case 0:  c1 = 0.f;                 c2 = 0.f;                 c3 = 0.f;                c4 = 0.f;              c5 = 0.f; break;
                case 1:  c1 = HC(1.0/5.0);         c2 = 0.f;                 c3 = 0.f;                c4 = 0.f;              c5 = 0.f; break;
                case 2:  c1 = HC(3.0/40.0);        c2 = HC(9.0/40.0);        c3 = 0.f;                c4 = 0.f;              c5 = 0.f; break;
                case 3:  c1 = HC(44.0/45.0);       c2 = HC(-56.0/15.0);      c3 = HC(32.0/9.0);       c4 = 0.f;              c5 = 0.f; break;
                case 4:  c1 = HC(19372.0/6561.0);  c2 = HC(-25360.0/2187.0); c3 = HC(64448.0/6561.0); c4 = HC(-212.0/729.0); c5 = 0.f; break;
                default: c1 = HC(9017.0/3168.0);   c2 = HC(-355.0/33.0);     c3 = HC(46732.0/5247.0); c4 = HC(49.0/176.0);   c5 = HC(-5103.0/18656.0); break;
            }

            // ---- build xi, fp16 hi/lo split, packed A fragments ----
            // A1[kc][j], j = e*2 + h : {row r0+8h, k-pair (16kc+8e+2c0, +1)}
            uint32_t A1[4][4], A2[4][4];
            #pragma unroll
            for (int kc = 0; kc < 4; kc++)
                #pragma unroll
                for (int e = 0; e < 2; e++)
                    #pragma unroll
                    for (int h = 0; h < 2; h++) {
                        const int m = kc * 4 + e * 2;
                        const int off = (r0 + 8 * h) * KSTR + 16 * kc + 8 * e + 2 * c0;
                        float2 v1 = *(const float2*)(k1w + off);
                        float2 v2 = *(const float2*)(k2w + off);
                        float2 v5 = *(const float2*)(k5w + off);
                        float a0 = xA[h][m], a1 = xA[h][m + 1];
                        a0 = fmaf(c1, v1.x, a0);            a1 = fmaf(c1, v1.y, a1);
                        a0 = fmaf(c2, v2.x, a0);            a1 = fmaf(c2, v2.y, a1);
                        a0 = fmaf(c3, k3A[h][m], a0);       a1 = fmaf(c3, k3A[h][m + 1], a1);
                        a0 = fmaf(c4, k4A[h][m], a0);       a1 = fmaf(c4, k4A[h][m + 1], a1);
                        a0 = fmaf(c5, v5.x, a0);            a1 = fmaf(c5, v5.y, a1);
                        __half2 hi = __floats2half2_rn(a0, a1);
                        float2 hb = __half22float2(hi);
                        __half2 lo = __floats2half2_rn(a0 - hb.x, a1 - hb.y);
                        A1[kc][e * 2 + h] = *(uint32_t*)&hi;
                        A2[kc][e * 2 + h] = *(uint32_t*)&lo;
                    }

            float* dst = (s == 0) ? k1w : (s == 1) ? k2w : (s == 4) ? k5w : scw;

            // ---- MMA: 4 groups x {z j, g j, z j+1, g j+1}, 3 passes, K=16 ----
            #pragma unroll
            for (int grp = 0; grp < 4; grp++) {
                const int nb0 = 16 * grp + r0;      // z tile j
                const int nb2 = nb0 + 8;            // z tile j+1
                const int nb1 = 64 + nb0;           // g tile j
                const int nb3 = 64 + nb2;           // g tile j+1

                float d0[4] = {0,0,0,0}, d1[4] = {0,0,0,0};
                float d2[4] = {0,0,0,0}, d3[4] = {0,0,0,0};

                #pragma unroll
                for (int kc = 0; kc < 4; kc++) {
                    const float4* Bp = BqT + (size_t)(kc * 4) * BQS;
                    float4 q0 = Bp[nb0];   // {B1 pair k0, B1 pair k0+8, B2 pair k0, B2 pair k0+8}
                    float4 q1 = Bp[nb1];
                    float4 q2 = Bp[nb2];
                    float4 q3 = Bp[nb3];

                    mma16(d0, A1[kc], __float_as_uint(q0.x), __float_as_uint(q0.y));  // HH
                    mma16(d1, A1[kc], __float_as_uint(q1.x), __float_as_uint(q1.y));
                    mma16(d2, A1[kc], __float_as_uint(q2.x), __float_as_uint(q2.y));
                    mma16(d3, A1[kc], __float_as_uint(q3.x), __float_as_uint(q3.y));
                    mma16(d0, A1[kc], __float_as_uint(q0.z), __float_as_uint(q0.w));  // HL
                    mma16(d1, A1[kc], __float_as_uint(q1.z), __float_as_uint(q1.w));
                    mma16(d2, A1[kc], __float_as_uint(q2.z), __float_as_uint(q2.w));
                    mma16(d3, A1[kc], __float_as_uint(q3.z), __float_as_uint(q3.w));
                    mma16(d0, A2[kc], __float_as_uint(q0.x), __float_as_uint(q0.y));  // LH
                    mma16(d1, A2[kc], __float_as_uint(q1.x), __float_as_uint(q1.y));
                    mma16(d2, A2[kc], __float_as_uint(q2.x), __float_as_uint(q2.y));
                    mma16(d3, A2[kc], __float_as_uint(q3.x), __float_as_uint(q3.y));
                }

                const int nb = 16 * grp;
                {
                    float bga = BG[nb + 2 * c0], bgb = BG[nb + 2 * c0 + 1];
                    float kv0 = gelu_f(d0[0]) * timefac_f(d1[0] + bga);
                    float kv1 = gelu_f(d0[1]) * timefac_f(d1[1] + bgb);
                    float kv2 = gelu_f(d0[2]) * timefac_f(d1[2] + bga);
                    float kv3 = gelu_f(d0[3]) * timefac_f(d1[3] + bgb);
                    *(float2*)&dst[r0 * KSTR + nb + 2 * c0]       = make_float2(kv0, kv1);
                    *(float2*)&dst[(r0 + 8) * KSTR + nb + 2 * c0] = make_float2(kv2, kv3);
                }
                {
                    float bga = BG[nb + 8 + 2 * c0], bgb = BG[nb + 8 + 2 * c0 + 1];
                    float kv0 = gelu_f(d2[0]) * timefac_f(d3[0] + bga);
                    float kv1 = gelu_f(d2[1]) * timefac_f(d3[1] + bgb);
                    float kv2 = gelu_f(d2[2]) * timefac_f(d3[2] + bga);
                    float kv3 = gelu_f(d2[3]) * timefac_f(d3[3] + bgb);
                    *(float2*)&dst[r0 * KSTR + nb + 8 + 2 * c0]       = make_float2(kv0, kv1);
                    *(float2*)&dst[(r0 + 8) * KSTR + nb + 8 + 2 * c0] = make_float2(kv2, kv3);
                }
            }

            __syncwarp();

            // ---- stage epilogue (paired loads) ----
            if (s == 2) {
                #pragma unroll
                for (int h = 0; h < 2; h++)
                    #pragma unroll
                    for (int kc = 0; kc < 4; kc++)
                        #pragma unroll
                        for (int e = 0; e < 2; e++) {
                            const int m = kc * 4 + e * 2;
                            float2 v = *(const float2*)(scw + (r0 + 8 * h) * KSTR + 16 * kc + 8 * e + 2 * c0);
                            k3A[h][m] = v.x; k3A[h][m + 1] = v.y;
                        }
            } else if (s == 3) {
                #pragma unroll
                for (int h = 0; h < 2; h++)
                    #pragma unroll
                    for (int kc = 0; kc < 4; kc++)
                        #pragma unroll
                        for (int e = 0; e < 2; e++) {
                            const int m = kc * 4 + e * 2;
                            float2 v = *(const float2*)(scw + (r0 + 8 * h) * KSTR + 16 * kc + 8 * e + 2 * c0);
                            k4A[h][m] = v.x; k4A[h][m + 1] = v.y;
                        }
            } else if (s == 5) {
                #pragma unroll
                for (int h = 0; h < 2; h++)
                    #pragma unroll
                    for (int kc = 0; kc < 4; kc++)
                        #pragma unroll
                        for (int e = 0; e < 2; e++) {
                            const int m = kc * 4 + e * 2;
                            const int off = (r0 + 8 * h) * KSTR + 16 * kc + 8 * e + 2 * c0;
                            float2 v1 = *(const float2*)(k1w + off);
                            float2 v5 = *(const float2*)(k5w + off);
                            float2 v6 = *(const float2*)(scw + off);
                            float a0 = xA[h][m], a1 = xA[h][m + 1];
                            a0 = fmaf(B0c, v1.x, a0);           a1 = fmaf(B0c, v1.y, a1);
                            a0 = fmaf(B2c, k3A[h][m], a0);      a1 = fmaf(B2c, k3A[h][m + 1], a1);
                            a0 = fmaf(B3c, k4A[h][m], a0);      a1 = fmaf(B3c, k4A[h][m + 1], a1);
                            a0 = fmaf(B4c, v5.x, a0);           a1 = fmaf(B4c, v5.y, a1);
                            xA[h][m]     = fmaf(B5c, v6.x, a0);
                            xA[h][m + 1] = fmaf(B5c, v6.y, a1);
                        }
            }
            __syncwarp();
        }
    }

    // ---- spike output ----
    #pragma unroll
    for (int h = 0; h < 2; h++) {
        int rr = rowbase + r0 + 8 * h;
        if (rr < batch) {
            #pragma unroll
            for (int kc = 0; kc < 4; kc++)
                #pragma unroll
                for (int e = 0; e < 2; e++) {
                    const int m = kc * 4 + e * 2;
                    const int col = 16 * kc + 8 * e + 2 * c0;
                    float2 o;
                    o.x = ((xA[h][m]     - 0.3f) > 0.0f) ? 1.0f : 0.0f;
                    o.y = ((xA[h][m + 1] - 0.3f) > 0.0f) ? 1.0f : 0.0f;
                    *(float2*)(out + (size_t)rr * 64 + col) = o;
                }
        }
    }
}

extern "C" void kernel_launch(void* const* d_in, const int* in_sizes, int n_in,
                              void* d_out, int out_size)
{
    const float* x  = (const float*)d_in[0];   // [batch, 64]
    const float* W  = (const float*)d_in[1];   // [64, 64]
    const float* Wg = (const float*)d_in[2];   // [64, 64]
    const float* bg = (const float*)d_in[3];   // [64]
    float* out = (float*)d_out;

    const int smem_bytes = SMEM_FLOATS * 4;
    cudaFuncSetAttribute(lif_hmma_kernel, cudaFuncAttributeMaxDynamicSharedMemorySize, smem_bytes);

    int batch = in_sizes[0] / 64;
    int grid = (batch + 127) / 128;
    lif_hmma_kernel<<<grid, THREADS, smem_bytes>>>(x, W, Wg, bg, out, batch);
}